// round 2
// baseline (speedup 1.0000x reference)
#include <cuda_runtime.h>

#define Bb 32
#define Nn 1024
#define TDd 32
#define CINc 66
#define CSTR 80
#define EDd 10
#define OGg 128
#define OUu 64
#define COG (CINc*OGg)   // 8448
#define COU (CINc*OUu)   // 4224

// ---------------- scratch (device globals; no runtime allocation) ----------------
__device__ float g_ins [Bb*Nn*CSTR];
__device__ float g_nv1 [Bb*Nn*TDd];
__device__ float g_nv2 [Bb*Nn*TDd];
__device__ float g_adj [(size_t)Bb*Nn*Nn];   // relu(M - M^T), 134 MB
__device__ float g_rowsum[Bb*Nn];
__device__ float g_ax  [Bb*Nn*CSTR];
__device__ float g_cand[Bb*Nn*CSTR];
__device__ float g_axc [Bb*Nn*CSTR];
__device__ float g_Wg0 [Nn*COG];
__device__ float g_Wg1 [Nn*COG];
__device__ float g_Wu0 [Nn*COU];
__device__ float g_Wu1 [Nn*COU];
__device__ float g_bg  [Nn*OGg];
__device__ float g_bu  [Nn*OUu];
__device__ float g_r   [Bb*Nn*OUu];

__device__ __forceinline__ float sigm(float v){ return 1.f/(1.f+__expf(-v)); }

// ---------------- K0: rowsum init (the +I of _preprocess) ----------------
__global__ void k_init(){
    int i = blockIdx.x*blockDim.x + threadIdx.x;
    if (i < Bb*Nn) g_rowsum[i] = 1.f;
}

// ---------------- K1: build ins (padded), run both tiny MLPs, produce nv1/nv2 ----
__global__ __launch_bounds__(128) void k_prep(
    const float* __restrict__ x, const float* __restrict__ st,
    const float* __restrict__ ne0, const float* __restrict__ ne1,
    const float* __restrict__ w11, const float* __restrict__ b11,
    const float* __restrict__ w12, const float* __restrict__ b12,
    const float* __restrict__ w13, const float* __restrict__ b13,
    const float* __restrict__ w21, const float* __restrict__ b21,
    const float* __restrict__ w22, const float* __restrict__ b22,
    const float* __restrict__ w23, const float* __restrict__ b23)
{
    __shared__ float sw11[1056], sw21[1056];
    __shared__ float sb11[16], sb21[16];
    __shared__ float sw12[32], sw22[32], sb12[2], sb22[2];
    __shared__ float sw13[64], sw23[64], sb13[32], sb23[32];
    __shared__ float sv[128*67];   // per-thread 66-wide input row, stride 67 (conflict-free)

    int t = threadIdx.x;
    for (int i = t; i < 1056; i += 128){ sw11[i] = w11[i]; sw21[i] = w21[i]; }
    if (t < 16){ sb11[t] = b11[t]; sb21[t] = b21[t]; }
    if (t < 32){
        sw12[t] = w12[t]; sw22[t] = w22[t];
        sw13[t] = w13[t]; sw23[t] = w23[t];
        sw13[32+t] = w13[32+t]; sw23[32+t] = w23[32+t];
        sb13[t] = b13[t]; sb23[t] = b23[t];
    }
    if (t < 2){ sb12[t] = b12[t]; sb22[t] = b22[t]; }

    int idx0 = blockIdx.x*128;          // 128 (b,n) rows per block, grid = 256
    // x part: 2 cols
    for (int e = t; e < 256; e += 128){
        int r = e >> 1, c = e & 1;
        float v = x[idx0*2 + e];
        sv[r*67 + c] = v;
        g_ins[(size_t)(idx0+r)*CSTR + c] = v;
    }
    // state part: 64 cols, coalesced
    for (int e = t; e < 128*64; e += 128){
        int r = e >> 6, c = e & 63;
        float v = st[(size_t)idx0*64 + e];
        sv[r*67 + 2 + c] = v;
        g_ins[(size_t)(idx0+r)*CSTR + 2 + c] = v;
    }
    // pad cols 66..79 = 0
    for (int e = t; e < 128*14; e += 128){
        int r = e/14, c = 66 + e%14;
        g_ins[(size_t)(idx0+r)*CSTR + c] = 0.f;
    }
    __syncthreads();

    int idx = idx0 + t;
    int b = idx >> 10;
    const float* vrow = &sv[t*67];

    // fc1 -> nv1
    {
        float h1[16];
        #pragma unroll
        for (int j = 0; j < 16; j++){
            float a = sb11[j];
            for (int i = 0; i < 66; i++) a += vrow[i]*sw11[i*16+j];
            h1[j] = sigm(a);
        }
        float a0 = sb12[0], a1 = sb12[1];
        #pragma unroll
        for (int j = 0; j < 16; j++){ a0 += h1[j]*sw12[j*2]; a1 += h1[j]*sw12[j*2+1]; }
        float h2a = sigm(a0), h2b = sigm(a1);
        #pragma unroll
        for (int o = 0; o < 32; o++){
            float f = sb13[o] + h2a*sw13[o] + h2b*sw13[32+o];
            g_nv1[(size_t)idx*TDd + o] = tanhf(ne0[b*TDd + o]*f);
        }
    }
    // fc2 -> nv2
    {
        float h1[16];
        #pragma unroll
        for (int j = 0; j < 16; j++){
            float a = sb21[j];
            for (int i = 0; i < 66; i++) a += vrow[i]*sw21[i*16+j];
            h1[j] = sigm(a);
        }
        float a0 = sb22[0], a1 = sb22[1];
        #pragma unroll
        for (int j = 0; j < 16; j++){ a0 += h1[j]*sw22[j*2]; a1 += h1[j]*sw22[j*2+1]; }
        float h2a = sigm(a0), h2b = sigm(a1);
        #pragma unroll
        for (int o = 0; o < 32; o++){
            float f = sb23[o] + h2a*sw23[o] + h2b*sw23[32+o];
            g_nv2[(size_t)idx*TDd + o] = tanhf(ne1[b*TDd + o]*f);
        }
    }
}

// ---------------- K2: effective per-node weights: out{0,1}[n,c] = sum_d ne2[n,d]*(pool[d,k,c]+pool[d,k+2,c])
template<int CO, bool GATE>
__global__ __launch_bounds__(128) void k_wmix(const float* __restrict__ pool,
                                              const float* __restrict__ ne2)
{
    __shared__ float sne[64*EDd];
    int t = threadIdx.x;
    int row0 = blockIdx.y*64;
    for (int i = t; i < 64*EDd; i += 128) sne[i] = ne2[row0*EDd + i];
    __syncthreads();

    int col = blockIdx.x*128 + t;   // grid sized so col < CO exactly
    float ga[EDd], gb[EDd];
    #pragma unroll
    for (int d = 0; d < EDd; d++){
        ga[d] = pool[(size_t)(d*4+0)*CO + col] + pool[(size_t)(d*4+2)*CO + col];
        gb[d] = pool[(size_t)(d*4+1)*CO + col] + pool[(size_t)(d*4+3)*CO + col];
    }
    float* o0 = GATE ? g_Wg0 : g_Wu0;
    float* o1 = GATE ? g_Wg1 : g_Wu1;
    for (int r = 0; r < 64; r++){
        float a0 = 0.f, a1 = 0.f;
        #pragma unroll
        for (int d = 0; d < EDd; d++){ float e = sne[r*EDd+d]; a0 += e*ga[d]; a1 += e*gb[d]; }
        o0[(size_t)(row0+r)*CO + col] = a0;
        o1[(size_t)(row0+r)*CO + col] = a1;
    }
}

template<int OUT, bool GATE>
__global__ void k_bias(const float* __restrict__ bpool, const float* __restrict__ ne2)
{
    int n = blockIdx.x, o = threadIdx.x;
    float a = 0.f;
    #pragma unroll
    for (int d = 0; d < EDd; d++) a += ne2[n*EDd+d]*bpool[d*OUT+o];
    (GATE ? g_bg : g_bu)[n*OUT + o] = a;
}

// ---------------- K3: adjrelu = relu(nv1 nv2^T - nv2 nv1^T) + rowsum accumulation ----
__global__ __launch_bounds__(256) void k_adj(){
    int b  = blockIdx.z;
    int r0 = blockIdx.y*64;
    int c0 = blockIdx.x*64;
    __shared__ float s1r[64][33], s2r[64][33], s1c[64][33], s2c[64][33];
    int t = threadIdx.x;
    const float* p1 = g_nv1 + (size_t)b*Nn*TDd;
    const float* p2 = g_nv2 + (size_t)b*Nn*TDd;
    for (int e = t; e < 2048; e += 256){
        int r = e >> 5, k = e & 31;
        s1r[r][k] = p1[(r0+r)*TDd + k];
        s2r[r][k] = p2[(r0+r)*TDd + k];
        s1c[r][k] = p1[(c0+r)*TDd + k];
        s2c[r][k] = p2[(c0+r)*TDd + k];
    }
    __syncthreads();

    int tx = t & 15, ty = t >> 4;
    float acc[4][4] = {};
    #pragma unroll 8
    for (int k = 0; k < 32; k++){
        float a1[4], a2[4], c1[4], c2[4];
        #pragma unroll
        for (int i = 0; i < 4; i++){ a1[i] = s1r[ty*4+i][k]; a2[i] = s2r[ty*4+i][k]; }
        #pragma unroll
        for (int j = 0; j < 4; j++){ c2[j] = s2c[tx*4+j][k]; c1[j] = s1c[tx*4+j][k]; }
        #pragma unroll
        for (int i = 0; i < 4; i++)
            #pragma unroll
            for (int j = 0; j < 4; j++)
                acc[i][j] += a1[i]*c2[j] - a2[i]*c1[j];
    }

    float* out = g_adj + ((size_t)b*Nn + r0)*Nn + c0;
    #pragma unroll
    for (int i = 0; i < 4; i++){
        float rs = 0.f;
        #pragma unroll
        for (int j = 0; j < 4; j++){
            float v = fmaxf(acc[i][j], 0.f);
            out[(size_t)(ty*4+i)*Nn + tx*4+j] = v;
            rs += v;
        }
        rs += __shfl_xor_sync(0xffffffffu, rs, 1);
        rs += __shfl_xor_sync(0xffffffffu, rs, 2);
        rs += __shfl_xor_sync(0xffffffffu, rs, 4);
        rs += __shfl_xor_sync(0xffffffffu, rs, 8);
        if (tx == 0) atomicAdd(&g_rowsum[b*Nn + r0 + ty*4 + i], rs);
    }
}

// ---------------- K4/K7: Y = (adjrelu @ X + X) / rowsum   (X stride 80, all 80 cols) ----
template<bool SECOND>
__global__ __launch_bounds__(256) void k_spmm(){
    const float* X = SECOND ? g_cand : g_ins;
    float*       Y = SECOND ? g_axc  : g_ax;
    int b = blockIdx.y;
    int row0 = blockIdx.x*128;
    __shared__ float sA[128*33];
    __shared__ float sX[32*CSTR];
    int t = threadIdx.x, tx = t & 15, ty = t >> 4;
    float acc[8][5] = {};
    const float* Ab = g_adj + (size_t)b*Nn*Nn;
    const float* Xb = X + (size_t)b*Nn*CSTR;

    for (int kt = 0; kt < 32; kt++){
        int k0 = kt*32;
        #pragma unroll
        for (int p = 0; p < 16; p++){
            int e = t + p*256; int r = e >> 5, k = e & 31;
            sA[r*33 + k] = Ab[(size_t)(row0+r)*Nn + k0 + k];
        }
        #pragma unroll
        for (int p = 0; p < 10; p++){
            int e = t + p*256;
            sX[e] = Xb[(size_t)k0*CSTR + e];
        }
        __syncthreads();
        #pragma unroll 4
        for (int k = 0; k < 32; k++){
            float a[8], xv[5];
            #pragma unroll
            for (int i = 0; i < 8; i++) a[i] = sA[(ty*8+i)*33 + k];
            #pragma unroll
            for (int j = 0; j < 5; j++) xv[j] = sX[k*CSTR + tx*5 + j];
            #pragma unroll
            for (int i = 0; i < 8; i++)
                #pragma unroll
                for (int j = 0; j < 5; j++)
                    acc[i][j] += a[i]*xv[j];
        }
        __syncthreads();
    }
    #pragma unroll
    for (int i = 0; i < 8; i++){
        int r = row0 + ty*8 + i;
        float inv = 1.f/g_rowsum[b*Nn + r];
        #pragma unroll
        for (int j = 0; j < 5; j++){
            int c = tx*5 + j;
            Y[((size_t)b*Nn + r)*CSTR + c] = (acc[i][j] + Xb[(size_t)r*CSTR + c])*inv;
        }
    }
}

// ---------------- K5: gate node-GEMM -> z,r; builds cand and stores r ----------------
__global__ __launch_bounds__(128) void k_gate(const float* __restrict__ x,
                                              const float* __restrict__ state)
{
    extern __shared__ float sm[];
    float* sW0 = sm;             // 8448
    float* sW1 = sm + COG;       // 8448
    float* sX  = sm + 2*COG;     // 2112
    float* sAX = sm + 2*COG + 2112;
    int n = blockIdx.x, t = threadIdx.x;
    int bg = t >> 5, og = t & 31;

    {
        float4* d0 = (float4*)sW0; const float4* s0 = (const float4*)(g_Wg0 + (size_t)n*COG);
        float4* d1 = (float4*)sW1; const float4* s1 = (const float4*)(g_Wg1 + (size_t)n*COG);
        for (int e = t; e < COG/4; e += 128){ d0[e] = s0[e]; d1[e] = s1[e]; }
    }
    for (int e = t; e < 32*66; e += 128){
        int bi = e/66, i = e%66;
        sX [e] = g_ins[((size_t)bi*Nn + n)*CSTR + i];
        sAX[e] = g_ax [((size_t)bi*Nn + n)*CSTR + i];
    }
    __syncthreads();

    float4 acc[8] = {};
    #pragma unroll 2
    for (int i = 0; i < 66; i++){
        float4 w0 = ((const float4*)sW0)[i*32 + og];
        float4 w1 = ((const float4*)sW1)[i*32 + og];
        #pragma unroll
        for (int bb = 0; bb < 8; bb++){
            int bi = bg*8 + bb;
            float xv = sX[bi*66 + i], av = sAX[bi*66 + i];
            acc[bb].x += xv*w0.x + av*w1.x;
            acc[bb].y += xv*w0.y + av*w1.y;
            acc[bb].z += xv*w0.z + av*w1.z;
            acc[bb].w += xv*w0.w + av*w1.w;
        }
    }
    float4 bias = *(const float4*)(g_bg + n*OGg + og*4);
    int o0 = og*4;
    #pragma unroll
    for (int bb = 0; bb < 8; bb++){
        int bi = bg*8 + bb;
        size_t bn = (size_t)bi*Nn + n;
        float vals[4] = { acc[bb].x + bias.x, acc[bb].y + bias.y,
                          acc[bb].z + bias.z, acc[bb].w + bias.w };
        #pragma unroll
        for (int c = 0; c < 4; c++){
            float zz = sigm(vals[c]);
            int o = o0 + c;
            if (o < 64) g_cand[bn*CSTR + 2 + o] = zz * state[bn*64 + o];
            else        g_r  [bn*64 + (o - 64)] = zz;
        }
    }
    if (og == 0){
        #pragma unroll
        for (int bb = 0; bb < 8; bb++){
            size_t bn = (size_t)(bg*8 + bb)*Nn + n;
            g_cand[bn*CSTR + 0] = x[bn*2 + 0];
            g_cand[bn*CSTR + 1] = x[bn*2 + 1];
            #pragma unroll
            for (int c = 66; c < 80; c++) g_cand[bn*CSTR + c] = 0.f;
        }
    }
}

// ---------------- K8: upd node-GEMM -> hc; final out = r*state + (1-r)*hc ----------------
__global__ __launch_bounds__(128) void k_upd(const float* __restrict__ state,
                                             float* __restrict__ out)
{
    extern __shared__ float sm[];
    float* sW0 = sm;             // 4224
    float* sW1 = sm + COU;       // 4224
    float* sX  = sm + 2*COU;     // 2112
    float* sAX = sm + 2*COU + 2112;
    int n = blockIdx.x, t = threadIdx.x;
    int bg = t >> 5, og = t & 31;

    {
        float4* d0 = (float4*)sW0; const float4* s0 = (const float4*)(g_Wu0 + (size_t)n*COU);
        float4* d1 = (float4*)sW1; const float4* s1 = (const float4*)(g_Wu1 + (size_t)n*COU);
        for (int e = t; e < COU/4; e += 128){ d0[e] = s0[e]; d1[e] = s1[e]; }
    }
    for (int e = t; e < 32*66; e += 128){
        int bi = e/66, i = e%66;
        sX [e] = g_cand[((size_t)bi*Nn + n)*CSTR + i];
        sAX[e] = g_axc [((size_t)bi*Nn + n)*CSTR + i];
    }
    __syncthreads();

    float2 acc[8] = {};
    #pragma unroll 2
    for (int i = 0; i < 66; i++){
        float2 w0 = ((const float2*)sW0)[i*32 + og];
        float2 w1 = ((const float2*)sW1)[i*32 + og];
        #pragma unroll
        for (int bb = 0; bb < 8; bb++){
            int bi = bg*8 + bb;
            float xv = sX[bi*66 + i], av = sAX[bi*66 + i];
            acc[bb].x += xv*w0.x + av*w1.x;
            acc[bb].y += xv*w0.y + av*w1.y;
        }
    }
    float2 bias = ((const float2*)(g_bu + n*OUu))[og];
    #pragma unroll
    for (int bb = 0; bb < 8; bb++){
        int bi = bg*8 + bb;
        size_t bn = (size_t)bi*Nn + n;
        #pragma unroll
        for (int c = 0; c < 2; c++){
            int o = og*2 + c;
            float hc = tanhf((c ? acc[bb].y + bias.y : acc[bb].x + bias.x));
            float rr = g_r[bn*64 + o];
            float sv = state[bn*64 + o];
            out[bn*64 + o] = rr*sv + (1.f - rr)*hc;
        }
    }
}

// ---------------- launcher ----------------
extern "C" void kernel_launch(void* const* d_in, const int* in_sizes, int n_in,
                              void* d_out, int out_size)
{
    const float* x      = (const float*)d_in[0];
    const float* state  = (const float*)d_in[1];
    const float* ne0    = (const float*)d_in[2];
    const float* ne1    = (const float*)d_in[3];
    const float* ne2    = (const float*)d_in[4];
    const float* f1w1   = (const float*)d_in[5];
    const float* f1b1   = (const float*)d_in[6];
    const float* f1w2   = (const float*)d_in[7];
    const float* f1b2   = (const float*)d_in[8];
    const float* f1w3   = (const float*)d_in[9];
    const float* f1b3   = (const float*)d_in[10];
    const float* f2w1   = (const float*)d_in[11];
    const float* f2b1   = (const float*)d_in[12];
    const float* f2w2   = (const float*)d_in[13];
    const float* f2b2   = (const float*)d_in[14];
    const float* f2w3   = (const float*)d_in[15];
    const float* f2b3   = (const float*)d_in[16];
    const float* gate_w = (const float*)d_in[17];
    const float* gate_b = (const float*)d_in[18];
    const float* upd_w  = (const float*)d_in[19];
    const float* upd_b  = (const float*)d_in[20];
    float* out = (float*)d_out;

    cudaFuncSetAttribute(k_gate, cudaFuncAttributeMaxDynamicSharedMemorySize, (2*COG + 2*2112)*4);
    cudaFuncSetAttribute(k_upd,  cudaFuncAttributeMaxDynamicSharedMemorySize, (2*COU + 2*2112)*4);

    k_init<<<128, 256>>>();
    k_prep<<<256, 128>>>(x, state, ne0, ne1,
                         f1w1, f1b1, f1w2, f1b2, f1w3, f1b3,
                         f2w1, f2b1, f2w2, f2b2, f2w3, f2b3);
    k_wmix<COG, true ><<<dim3(COG/128, Nn/64), 128>>>(gate_w, ne2);
    k_wmix<COU, false><<<dim3(COU/128, Nn/64), 128>>>(upd_w,  ne2);
    k_bias<OGg, true ><<<Nn, OGg>>>(gate_b, ne2);
    k_bias<OUu, false><<<Nn, OUu>>>(upd_b,  ne2);
    k_adj<<<dim3(16, 16, Bb), 256>>>();
    k_spmm<false><<<dim3(8, Bb), 256>>>();
    k_gate<<<Nn, 128, (2*COG + 2*2112)*4>>>(x, state);
    k_spmm<true><<<dim3(8, Bb), 256>>>();
    k_upd<<<Nn, 128, (2*COU + 2*2112)*4>>>(state, out);
}

// round 3
// speedup vs baseline: 1.0615x; 1.0615x over previous
#include <cuda_runtime.h>

#define Bb 32
#define Nn 1024
#define TDd 32
#define CINc 66
#define CSTR 80
#define EDd 10
#define OGg 128
#define OUu 64
#define COG (CINc*OGg)   // 8448
#define COU (CINc*OUu)   // 4224

typedef unsigned long long ull;

// ---------------- scratch (device globals; no runtime allocation) ----------------
__device__ float g_ins [Bb*Nn*CSTR];
__device__ float g_p   [Bb*Nn*64];           // [nv1 | -nv2]
__device__ float g_q   [Bb*Nn*64];           // [nv2 |  nv1]
__device__ float g_adj [(size_t)Bb*Nn*Nn];   // relu(M - M^T), 134 MB
__device__ float g_ax  [Bb*Nn*CSTR];
__device__ float g_cand[Bb*Nn*CSTR];
__device__ float g_axc [Bb*Nn*CSTR];
__device__ float g_Wg0 [Nn*COG];
__device__ float g_Wg1 [Nn*COG];
__device__ float g_Wu0 [Nn*COU];
__device__ float g_Wu1 [Nn*COU];
__device__ float g_bg  [Nn*OGg];
__device__ float g_bu  [Nn*OUu];
__device__ float g_r   [Bb*Nn*OUu];

__device__ __forceinline__ float sigm(float v){ return 1.f/(1.f+__expf(-v)); }

// ---- packed fp32x2 helpers (sm_103a FFMA2) ----
__device__ __forceinline__ void ffma2(ull& d, ull a, ull b){
    asm("fma.rn.f32x2 %0, %1, %2, %0;" : "+l"(d) : "l"(a), "l"(b));
}
__device__ __forceinline__ ull dup2(float v){
    ull r; asm("mov.b64 %0, {%1, %1};" : "=l"(r) : "f"(v)); return r;
}
__device__ __forceinline__ float2 unpk(ull v){
    float2 f; asm("mov.b64 {%0, %1}, %2;" : "=f"(f.x), "=f"(f.y) : "l"(v)); return f;
}

// ---------------- K1: build ins (padded, col79=1), tiny MLPs -> p,q ----
__global__ __launch_bounds__(128) void k_prep(
    const float* __restrict__ x, const float* __restrict__ st,
    const float* __restrict__ ne0, const float* __restrict__ ne1,
    const float* __restrict__ w11, const float* __restrict__ b11,
    const float* __restrict__ w12, const float* __restrict__ b12,
    const float* __restrict__ w13, const float* __restrict__ b13,
    const float* __restrict__ w21, const float* __restrict__ b21,
    const float* __restrict__ w22, const float* __restrict__ b22,
    const float* __restrict__ w23, const float* __restrict__ b23)
{
    __shared__ float sw11[1056], sw21[1056];
    __shared__ float sb11[16], sb21[16];
    __shared__ float sw12[32], sw22[32], sb12[2], sb22[2];
    __shared__ float sw13[64], sw23[64], sb13[32], sb23[32];
    __shared__ float sv[128*67];

    int t = threadIdx.x;
    for (int i = t; i < 1056; i += 128){ sw11[i] = w11[i]; sw21[i] = w21[i]; }
    if (t < 16){ sb11[t] = b11[t]; sb21[t] = b21[t]; }
    if (t < 32){
        sw12[t] = w12[t]; sw22[t] = w22[t];
        sw13[t] = w13[t]; sw23[t] = w23[t];
        sw13[32+t] = w13[32+t]; sw23[32+t] = w23[32+t];
        sb13[t] = b13[t]; sb23[t] = b23[t];
    }
    if (t < 2){ sb12[t] = b12[t]; sb22[t] = b22[t]; }

    int idx0 = blockIdx.x*128;
    for (int e = t; e < 256; e += 128){
        int r = e >> 1, c = e & 1;
        float v = x[idx0*2 + e];
        sv[r*67 + c] = v;
        g_ins[(size_t)(idx0+r)*CSTR + c] = v;
    }
    for (int e = t; e < 128*64; e += 128){
        int r = e >> 6, c = e & 63;
        float v = st[(size_t)idx0*64 + e];
        sv[r*67 + 2 + c] = v;
        g_ins[(size_t)(idx0+r)*CSTR + 2 + c] = v;
    }
    for (int e = t; e < 128*14; e += 128){
        int r = e/14, c = 66 + e%14;
        g_ins[(size_t)(idx0+r)*CSTR + c] = (c == 79) ? 1.f : 0.f;  // ones-col for rowsum
    }
    __syncthreads();

    int idx = idx0 + t;
    int b = idx >> 10;
    const float* vrow = &sv[t*67];

    // fc1 -> nv1 : p[0..31] = nv1, q[32..63] = nv1
    {
        float h1[16];
        #pragma unroll
        for (int j = 0; j < 16; j++){
            float a = sb11[j];
            for (int i = 0; i < 66; i++) a += vrow[i]*sw11[i*16+j];
            h1[j] = sigm(a);
        }
        float a0 = sb12[0], a1 = sb12[1];
        #pragma unroll
        for (int j = 0; j < 16; j++){ a0 += h1[j]*sw12[j*2]; a1 += h1[j]*sw12[j*2+1]; }
        float h2a = sigm(a0), h2b = sigm(a1);
        #pragma unroll
        for (int o = 0; o < 32; o++){
            float f = sb13[o] + h2a*sw13[o] + h2b*sw13[32+o];
            float nv = tanhf(ne0[b*TDd + o]*f);
            g_p[(size_t)idx*64 + o] = nv;
            g_q[(size_t)idx*64 + 32 + o] = nv;
        }
    }
    // fc2 -> nv2 : p[32..63] = -nv2, q[0..31] = nv2
    {
        float h1[16];
        #pragma unroll
        for (int j = 0; j < 16; j++){
            float a = sb21[j];
            for (int i = 0; i < 66; i++) a += vrow[i]*sw21[i*16+j];
            h1[j] = sigm(a);
        }
        float a0 = sb22[0], a1 = sb22[1];
        #pragma unroll
        for (int j = 0; j < 16; j++){ a0 += h1[j]*sw22[j*2]; a1 += h1[j]*sw22[j*2+1]; }
        float h2a = sigm(a0), h2b = sigm(a1);
        #pragma unroll
        for (int o = 0; o < 32; o++){
            float f = sb23[o] + h2a*sw23[o] + h2b*sw23[32+o];
            float nv = tanhf(ne1[b*TDd + o]*f);
            g_p[(size_t)idx*64 + 32 + o] = -nv;
            g_q[(size_t)idx*64 + o] = nv;
        }
    }
}

// ---------------- K2: effective per-node weights ----------------
template<int CO, bool GATE>
__global__ __launch_bounds__(128) void k_wmix(const float* __restrict__ pool,
                                              const float* __restrict__ ne2)
{
    __shared__ float sne[64*EDd];
    int t = threadIdx.x;
    int row0 = blockIdx.y*64;
    for (int i = t; i < 64*EDd; i += 128) sne[i] = ne2[row0*EDd + i];
    __syncthreads();

    int col = blockIdx.x*128 + t;
    float ga[EDd], gb[EDd];
    #pragma unroll
    for (int d = 0; d < EDd; d++){
        ga[d] = pool[(size_t)(d*4+0)*CO + col] + pool[(size_t)(d*4+2)*CO + col];
        gb[d] = pool[(size_t)(d*4+1)*CO + col] + pool[(size_t)(d*4+3)*CO + col];
    }
    float* o0 = GATE ? g_Wg0 : g_Wu0;
    float* o1 = GATE ? g_Wg1 : g_Wu1;
    for (int r = 0; r < 64; r++){
        float a0 = 0.f, a1 = 0.f;
        #pragma unroll
        for (int d = 0; d < EDd; d++){ float e = sne[r*EDd+d]; a0 += e*ga[d]; a1 += e*gb[d]; }
        o0[(size_t)(row0+r)*CO + col] = a0;
        o1[(size_t)(row0+r)*CO + col] = a1;
    }
}

template<int OUT, bool GATE>
__global__ void k_bias(const float* __restrict__ bpool, const float* __restrict__ ne2)
{
    int n = blockIdx.x, o = threadIdx.x;
    float a = 0.f;
    #pragma unroll
    for (int d = 0; d < EDd; d++) a += ne2[n*EDd+d]*bpool[d*OUT+o];
    (GATE ? g_bg : g_bu)[n*OUT + o] = a;
}

// ---------------- K3: adjrelu = relu(p @ q^T)  (single GEMM, K=64, FFMA2) ----
// grid (16 colTiles, 8 rowTiles, Bb), block 256. Tile 128 rows x 64 cols.
// thread: tx = t&7 (cols: tx*2 + 16j + h, j<4), ty = t>>3 (rows ty*4+i, i<4)
__global__ __launch_bounds__(256) void k_adj(){
    __shared__ ull  sP[128*33];                  // dup-packed p rows per k-chunk
    __shared__ __align__(16) float sQ[32*66];    // q transposed [k][c]
    int b  = blockIdx.z;
    int r0 = blockIdx.y*128;
    int c0 = blockIdx.x*64;
    int t = threadIdx.x, tx = t & 7, ty = t >> 3;
    const float* Pb = g_p + (size_t)b*Nn*64;
    const float* Qb = g_q + (size_t)b*Nn*64;

    ull acc[4][4] = {};
    for (int kt = 0; kt < 2; kt++){
        int k0 = kt*32;
        #pragma unroll
        for (int p = 0; p < 16; p++){
            int e = t + p*256; int r = e >> 5, k = e & 31;
            sP[r*33 + k] = dup2(Pb[(size_t)(r0+r)*64 + k0 + k]);
        }
        #pragma unroll
        for (int p = 0; p < 8; p++){
            int e = t + p*256; int c = e >> 5, k = e & 31;
            sQ[k*66 + c] = Qb[(size_t)(c0+c)*64 + k0 + k];
        }
        __syncthreads();
        #pragma unroll 4
        for (int k = 0; k < 32; k++){
            ull a[4], qv[4];
            #pragma unroll
            for (int i = 0; i < 4; i++) a[i] = sP[(ty*4+i)*33 + k];
            #pragma unroll
            for (int j = 0; j < 4; j++) qv[j] = *(const ull*)&sQ[k*66 + tx*2 + 16*j];
            #pragma unroll
            for (int i = 0; i < 4; i++)
                #pragma unroll
                for (int j = 0; j < 4; j++)
                    ffma2(acc[i][j], a[i], qv[j]);
        }
        __syncthreads();
    }

    float* out = g_adj + ((size_t)b*Nn + r0)*Nn + c0;
    #pragma unroll
    for (int i = 0; i < 4; i++){
        #pragma unroll
        for (int j = 0; j < 4; j++){
            float2 v = unpk(acc[i][j]);
            v.x = fmaxf(v.x, 0.f); v.y = fmaxf(v.y, 0.f);
            *(float2*)&out[(size_t)(ty*4+i)*Nn + tx*2 + 16*j] = v;
        }
    }
}

// ---------------- K4/K7: Y = (adjrelu @ X + X) / rowsum, rowsum from ones-col 79 ----
// grid (8, Bb), block 256. Tile 128 rows x 80 cols.
// thread: tx = t&7 (cols tx*10 + 2j + h, j<5), ty = t>>3 (rows ty*4+i, i<4)
template<bool SECOND>
__global__ __launch_bounds__(256) void k_spmm(){
    const float* X = SECOND ? g_cand : g_ins;
    float*       Y = SECOND ? g_axc  : g_ax;
    __shared__ ull sA[128*33];                   // dup-packed A per k-chunk
    __shared__ __align__(16) float sX[32*CSTR];
    __shared__ float srs[128];
    int b = blockIdx.y;
    int row0 = blockIdx.x*128;
    int t = threadIdx.x, tx = t & 7, ty = t >> 3;
    const float* Ab = g_adj + (size_t)b*Nn*Nn;
    const float* Xb = X + (size_t)b*Nn*CSTR;

    ull acc[4][5] = {};
    for (int kt = 0; kt < 32; kt++){
        int k0 = kt*32;
        #pragma unroll
        for (int p = 0; p < 16; p++){
            int e = t + p*256; int r = e >> 5, k = e & 31;
            sA[r*33 + k] = dup2(Ab[(size_t)(row0+r)*Nn + k0 + k]);
        }
        #pragma unroll
        for (int p = 0; p < 10; p++){
            int e = t + p*256;
            sX[e] = Xb[(size_t)k0*CSTR + e];
        }
        __syncthreads();
        #pragma unroll 4
        for (int k = 0; k < 32; k++){
            ull a[4], xv[5];
            #pragma unroll
            for (int i = 0; i < 4; i++) a[i] = sA[(ty*4+i)*33 + k];
            #pragma unroll
            for (int j = 0; j < 5; j++) xv[j] = *(const ull*)&sX[k*CSTR + tx*10 + 2*j];
            #pragma unroll
            for (int i = 0; i < 4; i++)
                #pragma unroll
                for (int j = 0; j < 5; j++)
                    ffma2(acc[i][j], a[i], xv[j]);
        }
        __syncthreads();
    }

    // rowsum: col 79 = hi half of acc[i][4] on tx==7 (acc79 = rowsum-1)
    if (tx == 7){
        #pragma unroll
        for (int i = 0; i < 4; i++){
            float2 v = unpk(acc[i][4]);
            srs[ty*4 + i] = v.y + 1.f;
        }
    }
    __syncthreads();

    #pragma unroll
    for (int i = 0; i < 4; i++){
        int r = row0 + ty*4 + i;
        float inv = 1.f/srs[ty*4 + i];
        #pragma unroll
        for (int j = 0; j < 5; j++){
            int c = tx*10 + 2*j;
            float2 v  = unpk(acc[i][j]);
            float2 xr = *(const float2*)&Xb[(size_t)r*CSTR + c];
            float2 o; o.x = (v.x + xr.x)*inv; o.y = (v.y + xr.y)*inv;
            *(float2*)&Y[((size_t)b*Nn + r)*CSTR + c] = o;
        }
    }
}

// ---------------- K5: gate node-GEMM -> z,r; builds cand (col79=1) ----------------
__global__ __launch_bounds__(128) void k_gate(const float* __restrict__ x,
                                              const float* __restrict__ state)
{
    extern __shared__ float sm[];
    float* sW0 = sm;
    float* sW1 = sm + COG;
    float* sX  = sm + 2*COG;
    float* sAX = sm + 2*COG + 2112;
    int n = blockIdx.x, t = threadIdx.x;
    int bg = t >> 5, og = t & 31;

    {
        float4* d0 = (float4*)sW0; const float4* s0 = (const float4*)(g_Wg0 + (size_t)n*COG);
        float4* d1 = (float4*)sW1; const float4* s1 = (const float4*)(g_Wg1 + (size_t)n*COG);
        for (int e = t; e < COG/4; e += 128){ d0[e] = s0[e]; d1[e] = s1[e]; }
    }
    for (int e = t; e < 32*66; e += 128){
        int bi = e/66, i = e%66;
        sX [e] = g_ins[((size_t)bi*Nn + n)*CSTR + i];
        sAX[e] = g_ax [((size_t)bi*Nn + n)*CSTR + i];
    }
    __syncthreads();

    float4 acc[8] = {};
    #pragma unroll 2
    for (int i = 0; i < 66; i++){
        float4 w0 = ((const float4*)sW0)[i*32 + og];
        float4 w1 = ((const float4*)sW1)[i*32 + og];
        #pragma unroll
        for (int bb = 0; bb < 8; bb++){
            int bi = bg*8 + bb;
            float xv = sX[bi*66 + i], av = sAX[bi*66 + i];
            acc[bb].x += xv*w0.x + av*w1.x;
            acc[bb].y += xv*w0.y + av*w1.y;
            acc[bb].z += xv*w0.z + av*w1.z;
            acc[bb].w += xv*w0.w + av*w1.w;
        }
    }
    float4 bias = *(const float4*)(g_bg + n*OGg + og*4);
    int o0 = og*4;
    #pragma unroll
    for (int bb = 0; bb < 8; bb++){
        int bi = bg*8 + bb;
        size_t bn = (size_t)bi*Nn + n;
        float vals[4] = { acc[bb].x + bias.x, acc[bb].y + bias.y,
                          acc[bb].z + bias.z, acc[bb].w + bias.w };
        #pragma unroll
        for (int c = 0; c < 4; c++){
            float zz = sigm(vals[c]);
            int o = o0 + c;
            if (o < 64) g_cand[bn*CSTR + 2 + o] = zz * state[bn*64 + o];
            else        g_r  [bn*64 + (o - 64)] = zz;
        }
    }
    if (og == 0){
        #pragma unroll
        for (int bb = 0; bb < 8; bb++){
            size_t bn = (size_t)(bg*8 + bb)*Nn + n;
            g_cand[bn*CSTR + 0] = x[bn*2 + 0];
            g_cand[bn*CSTR + 1] = x[bn*2 + 1];
            #pragma unroll
            for (int c = 66; c < 80; c++) g_cand[bn*CSTR + c] = (c == 79) ? 1.f : 0.f;
        }
    }
}

// ---------------- K8: upd node-GEMM -> hc; final out ----------------
__global__ __launch_bounds__(128) void k_upd(const float* __restrict__ state,
                                             float* __restrict__ out)
{
    extern __shared__ float sm[];
    float* sW0 = sm;
    float* sW1 = sm + COU;
    float* sX  = sm + 2*COU;
    float* sAX = sm + 2*COU + 2112;
    int n = blockIdx.x, t = threadIdx.x;
    int bg = t >> 5, og = t & 31;

    {
        float4* d0 = (float4*)sW0; const float4* s0 = (const float4*)(g_Wu0 + (size_t)n*COU);
        float4* d1 = (float4*)sW1; const float4* s1 = (const float4*)(g_Wu1 + (size_t)n*COU);
        for (int e = t; e < COU/4; e += 128){ d0[e] = s0[e]; d1[e] = s1[e]; }
    }
    for (int e = t; e < 32*66; e += 128){
        int bi = e/66, i = e%66;
        sX [e] = g_cand[((size_t)bi*Nn + n)*CSTR + i];
        sAX[e] = g_axc [((size_t)bi*Nn + n)*CSTR + i];
    }
    __syncthreads();

    float2 acc[8] = {};
    #pragma unroll 2
    for (int i = 0; i < 66; i++){
        float2 w0 = ((const float2*)sW0)[i*32 + og];
        float2 w1 = ((const float2*)sW1)[i*32 + og];
        #pragma unroll
        for (int bb = 0; bb < 8; bb++){
            int bi = bg*8 + bb;
            float xv = sX[bi*66 + i], av = sAX[bi*66 + i];
            acc[bb].x += xv*w0.x + av*w1.x;
            acc[bb].y += xv*w0.y + av*w1.y;
        }
    }
    float2 bias = ((const float2*)(g_bu + n*OUu))[og];
    #pragma unroll
    for (int bb = 0; bb < 8; bb++){
        int bi = bg*8 + bb;
        size_t bn = (size_t)bi*Nn + n;
        #pragma unroll
        for (int c = 0; c < 2; c++){
            int o = og*2 + c;
            float hc = tanhf((c ? acc[bb].y + bias.y : acc[bb].x + bias.x));
            float rr = g_r[bn*64 + o];
            float sv = state[bn*64 + o];
            out[bn*64 + o] = rr*sv + (1.f - rr)*hc;
        }
    }
}

// ---------------- launcher ----------------
extern "C" void kernel_launch(void* const* d_in, const int* in_sizes, int n_in,
                              void* d_out, int out_size)
{
    const float* x      = (const float*)d_in[0];
    const float* state  = (const float*)d_in[1];
    const float* ne0    = (const float*)d_in[2];
    const float* ne1    = (const float*)d_in[3];
    const float* ne2    = (const float*)d_in[4];
    const float* f1w1   = (const float*)d_in[5];
    const float* f1b1   = (const float*)d_in[6];
    const float* f1w2   = (const float*)d_in[7];
    const float* f1b2   = (const float*)d_in[8];
    const float* f1w3   = (const float*)d_in[9];
    const float* f1b3   = (const float*)d_in[10];
    const float* f2w1   = (const float*)d_in[11];
    const float* f2b1   = (const float*)d_in[12];
    const float* f2w2   = (const float*)d_in[13];
    const float* f2b2   = (const float*)d_in[14];
    const float* f2w3   = (const float*)d_in[15];
    const float* f2b3   = (const float*)d_in[16];
    const float* gate_w = (const float*)d_in[17];
    const float* gate_b = (const float*)d_in[18];
    const float* upd_w  = (const float*)d_in[19];
    const float* upd_b  = (const float*)d_in[20];
    float* out = (float*)d_out;

    cudaFuncSetAttribute(k_gate, cudaFuncAttributeMaxDynamicSharedMemorySize, (2*COG + 2*2112)*4);
    cudaFuncSetAttribute(k_upd,  cudaFuncAttributeMaxDynamicSharedMemorySize, (2*COU + 2*2112)*4);

    k_prep<<<256, 128>>>(x, state, ne0, ne1,
                         f1w1, f1b1, f1w2, f1b2, f1w3, f1b3,
                         f2w1, f2b1, f2w2, f2b2, f2w3, f2b3);
    k_wmix<COG, true ><<<dim3(COG/128, Nn/64), 128>>>(gate_w, ne2);
    k_wmix<COU, false><<<dim3(COU/128, Nn/64), 128>>>(upd_w,  ne2);
    k_bias<OGg, true ><<<Nn, OGg>>>(gate_b, ne2);
    k_bias<OUu, false><<<Nn, OUu>>>(upd_b,  ne2);
    k_adj<<<dim3(16, 8, Bb), 256>>>();
    k_spmm<false><<<dim3(8, Bb), 256>>>();
    k_gate<<<Nn, 128, (2*COG + 2*2112)*4>>>(x, state);
    k_spmm<true><<<dim3(8, Bb), 256>>>();
    k_upd<<<Nn, 128, (2*COU + 2*2112)*4>>>(state, out);
}

// round 4
// speedup vs baseline: 1.1095x; 1.0452x over previous
#include <cuda_runtime.h>

#define Bb 32
#define Nn 1024
#define TDd 32
#define CINc 66
#define CSTR 80
#define EDd 10
#define OGg 128
#define OUu 64
#define COG (CINc*OGg)   // 8448
#define COU (CINc*OUu)   // 4224

typedef unsigned long long ull;

// ---------------- scratch ----------------
__device__ float g_ins [Bb*Nn*CSTR];
__device__ float g_p   [Bb*Nn*64];           // [nv1 | -nv2]
__device__ float g_q   [Bb*Nn*64];           // [nv2 |  nv1]
__device__ float g_adj [(size_t)Bb*Nn*Nn];
__device__ float g_ax  [Bb*Nn*CSTR];
__device__ float g_cand[Bb*Nn*CSTR];
__device__ float g_axc [Bb*Nn*CSTR];
__device__ float g_Wg0 [Nn*COG];
__device__ float g_Wg1 [Nn*COG];
__device__ float g_Wu0 [Nn*COU];
__device__ float g_Wu1 [Nn*COU];
__device__ float g_bg  [Nn*OGg];
__device__ float g_bu  [Nn*OUu];
__device__ float g_r   [Bb*Nn*OUu];

__device__ __forceinline__ float sigm(float v){ return 1.f/(1.f+__expf(-v)); }

__device__ __forceinline__ void ffma2(ull& d, ull a, ull b){
    asm("fma.rn.f32x2 %0, %1, %2, %0;" : "+l"(d) : "l"(a), "l"(b));
}
__device__ __forceinline__ float2 unpk(ull v){
    float2 f; asm("mov.b64 {%0, %1}, %2;" : "=f"(f.x), "=f"(f.y) : "l"(v)); return f;
}
__device__ __forceinline__ float hsum(ull v){ float2 f = unpk(v); return f.x + f.y; }

// ---------------- K1: build ins (col79=1), tiny MLPs -> p,q ----
__global__ __launch_bounds__(128) void k_prep(
    const float* __restrict__ x, const float* __restrict__ st,
    const float* __restrict__ ne0, const float* __restrict__ ne1,
    const float* __restrict__ w11, const float* __restrict__ b11,
    const float* __restrict__ w12, const float* __restrict__ b12,
    const float* __restrict__ w13, const float* __restrict__ b13,
    const float* __restrict__ w21, const float* __restrict__ b21,
    const float* __restrict__ w22, const float* __restrict__ b22,
    const float* __restrict__ w23, const float* __restrict__ b23)
{
    __shared__ float sw11[1056], sw21[1056];
    __shared__ float sb11[16], sb21[16];
    __shared__ float sw12[32], sw22[32], sb12[2], sb22[2];
    __shared__ float sw13[64], sw23[64], sb13[32], sb23[32];
    __shared__ float sv[128*67];

    int t = threadIdx.x;
    for (int i = t; i < 1056; i += 128){ sw11[i] = w11[i]; sw21[i] = w21[i]; }
    if (t < 16){ sb11[t] = b11[t]; sb21[t] = b21[t]; }
    if (t < 32){
        sw12[t] = w12[t]; sw22[t] = w22[t];
        sw13[t] = w13[t]; sw23[t] = w23[t];
        sw13[32+t] = w13[32+t]; sw23[32+t] = w23[32+t];
        sb13[t] = b13[t]; sb23[t] = b23[t];
    }
    if (t < 2){ sb12[t] = b12[t]; sb22[t] = b22[t]; }

    int idx0 = blockIdx.x*128;
    for (int e = t; e < 256; e += 128){
        int r = e >> 1, c = e & 1;
        float v = x[idx0*2 + e];
        sv[r*67 + c] = v;
        g_ins[(size_t)(idx0+r)*CSTR + c] = v;
    }
    for (int e = t; e < 128*64; e += 128){
        int r = e >> 6, c = e & 63;
        float v = st[(size_t)idx0*64 + e];
        sv[r*67 + 2 + c] = v;
        g_ins[(size_t)(idx0+r)*CSTR + 2 + c] = v;
    }
    for (int e = t; e < 128*14; e += 128){
        int r = e/14, c = 66 + e%14;
        g_ins[(size_t)(idx0+r)*CSTR + c] = (c == 79) ? 1.f : 0.f;
    }
    __syncthreads();

    int idx = idx0 + t;
    int b = idx >> 10;
    const float* vrow = &sv[t*67];

    {
        float h1[16];
        #pragma unroll
        for (int j = 0; j < 16; j++){
            float a = sb11[j];
            for (int i = 0; i < 66; i++) a += vrow[i]*sw11[i*16+j];
            h1[j] = sigm(a);
        }
        float a0 = sb12[0], a1 = sb12[1];
        #pragma unroll
        for (int j = 0; j < 16; j++){ a0 += h1[j]*sw12[j*2]; a1 += h1[j]*sw12[j*2+1]; }
        float h2a = sigm(a0), h2b = sigm(a1);
        #pragma unroll
        for (int o = 0; o < 32; o++){
            float f = sb13[o] + h2a*sw13[o] + h2b*sw13[32+o];
            float nv = tanhf(ne0[b*TDd + o]*f);
            g_p[(size_t)idx*64 + o] = nv;
            g_q[(size_t)idx*64 + 32 + o] = nv;
        }
    }
    {
        float h1[16];
        #pragma unroll
        for (int j = 0; j < 16; j++){
            float a = sb21[j];
            for (int i = 0; i < 66; i++) a += vrow[i]*sw21[i*16+j];
            h1[j] = sigm(a);
        }
        float a0 = sb22[0], a1 = sb22[1];
        #pragma unroll
        for (int j = 0; j < 16; j++){ a0 += h1[j]*sw22[j*2]; a1 += h1[j]*sw22[j*2+1]; }
        float h2a = sigm(a0), h2b = sigm(a1);
        #pragma unroll
        for (int o = 0; o < 32; o++){
            float f = sb23[o] + h2a*sw23[o] + h2b*sw23[32+o];
            float nv = tanhf(ne1[b*TDd + o]*f);
            g_p[(size_t)idx*64 + 32 + o] = -nv;
            g_q[(size_t)idx*64 + o] = nv;
        }
    }
}

// ---------------- K2: effective per-node weights ----------------
template<int CO, bool GATE>
__global__ __launch_bounds__(128) void k_wmix(const float* __restrict__ pool,
                                              const float* __restrict__ ne2)
{
    __shared__ float sne[64*EDd];
    int t = threadIdx.x;
    int row0 = blockIdx.y*64;
    for (int i = t; i < 64*EDd; i += 128) sne[i] = ne2[row0*EDd + i];
    __syncthreads();

    int col = blockIdx.x*128 + t;
    float ga[EDd], gb[EDd];
    #pragma unroll
    for (int d = 0; d < EDd; d++){
        ga[d] = pool[(size_t)(d*4+0)*CO + col] + pool[(size_t)(d*4+2)*CO + col];
        gb[d] = pool[(size_t)(d*4+1)*CO + col] + pool[(size_t)(d*4+3)*CO + col];
    }
    float* o0 = GATE ? g_Wg0 : g_Wu0;
    float* o1 = GATE ? g_Wg1 : g_Wu1;
    for (int r = 0; r < 64; r++){
        float a0 = 0.f, a1 = 0.f;
        #pragma unroll
        for (int d = 0; d < EDd; d++){ float e = sne[r*EDd+d]; a0 += e*ga[d]; a1 += e*gb[d]; }
        o0[(size_t)(row0+r)*CO + col] = a0;
        o1[(size_t)(row0+r)*CO + col] = a1;
    }
}

// merged gate+upd bias mix: block 192 (128 gate cols + 64 upd cols)
__global__ void k_biases(const float* __restrict__ bg_pool, const float* __restrict__ bu_pool,
                         const float* __restrict__ ne2)
{
    int n = blockIdx.x, t = threadIdx.x;
    float ne[EDd];
    #pragma unroll
    for (int d = 0; d < EDd; d++) ne[d] = ne2[n*EDd+d];
    if (t < 128){
        float a = 0.f;
        #pragma unroll
        for (int d = 0; d < EDd; d++) a += ne[d]*bg_pool[d*OGg+t];
        g_bg[n*OGg + t] = a;
    } else {
        int o = t - 128;
        float a = 0.f;
        #pragma unroll
        for (int d = 0; d < EDd; d++) a += ne[d]*bu_pool[d*OUu+o];
        g_bu[n*OUu + o] = a;
    }
}

// ---------------- K3: adjrelu = relu(p @ q^T), K=64, k-parity FFMA2 ----
// grid (8 colTiles, 8 rowTiles, Bb), block 256. Tile 128x128, thread 8x8.
// tx = t&15 -> cols tx+16g (g<8); ty = t>>4 -> rows ty*8+i (i<8).
#define ADJ_SP 66
__global__ __launch_bounds__(256, 1) void k_adj(){
    extern __shared__ float sm_adj[];
    float* sP = sm_adj;                 // [128][66]
    float* sQ = sm_adj + 128*ADJ_SP;    // [128][66] (rows = cols of tile)
    int b  = blockIdx.z;
    int r0 = blockIdx.y*128;
    int c0 = blockIdx.x*128;
    int t = threadIdx.x, tx = t & 15, ty = t >> 4;
    const float* Pb = g_p + (size_t)b*Nn*64;
    const float* Qb = g_q + (size_t)b*Nn*64;

    // stage full K=64 as float2
    #pragma unroll
    for (int p = 0; p < 16; p++){
        int e = t + p*256;              // 4096 float2 = 128x64
        int r = e >> 5, k2 = e & 31;
        float2 v = *(const float2*)&Pb[(size_t)(r0+r)*64 + 2*k2];
        *(float2*)&sP[r*ADJ_SP + 2*k2] = v;
        float2 w = *(const float2*)&Qb[(size_t)(c0+r)*64 + 2*k2];
        *(float2*)&sQ[r*ADJ_SP + 2*k2] = w;
    }
    __syncthreads();

    ull acc[8][8] = {};
    #pragma unroll 4
    for (int k2 = 0; k2 < 32; k2++){
        int kk = 2*k2;
        ull pv[8], qv[8];
        #pragma unroll
        for (int i = 0; i < 8; i++) pv[i] = *(const ull*)&sP[(ty*8+i)*ADJ_SP + kk];
        #pragma unroll
        for (int g = 0; g < 8; g++) qv[g] = *(const ull*)&sQ[(tx+16*g)*ADJ_SP + kk];
        #pragma unroll
        for (int i = 0; i < 8; i++)
            #pragma unroll
            for (int g = 0; g < 8; g++)
                ffma2(acc[i][g], pv[i], qv[g]);
    }

    float* out = g_adj + ((size_t)b*Nn + r0)*Nn + c0;
    #pragma unroll
    for (int i = 0; i < 8; i++){
        #pragma unroll
        for (int g = 0; g < 8; g++){
            out[(size_t)(ty*8+i)*Nn + tx + 16*g] = fmaxf(hsum(acc[i][g]), 0.f);
        }
    }
}

// ---------------- K4/K7: Y = (adj @ X + X)/rowsum, k-parity FFMA2 ----
// grid (8, Bb), block 128. Tile 128 rows x 80 cols, thread 8x10.
// tx = t&7 -> cols tx*10+j (j<10); ty = t>>3 -> rows ty*8+i (i<8).
#define SPA 34
template<bool SECOND>
__global__ __launch_bounds__(128, 1) void k_spmm(){
    const float* X = SECOND ? g_cand : g_ins;
    float*       Y = SECOND ? g_axc  : g_ax;
    __shared__ float sA [128*SPA];      // [row][k] stride 34
    __shared__ float sXT[CSTR*SPA];     // [col][k] stride 34 (transposed)
    __shared__ float srs[128];
    int b = blockIdx.y;
    int row0 = blockIdx.x*128;
    int t = threadIdx.x, tx = t & 7, ty = t >> 3;
    const float* Ab = g_adj + (size_t)b*Nn*Nn;
    const float* Xb = X + (size_t)b*Nn*CSTR;

    ull acc[8][10] = {};
    for (int kt = 0; kt < 32; kt++){
        int k0 = kt*32;
        // A tile: 128x32 as float2, coalesced
        #pragma unroll
        for (int p = 0; p < 16; p++){
            int e = t + p*128;          // 2048 float2
            int r = e >> 4, k2 = e & 15;
            float2 v = *(const float2*)&Ab[(size_t)(row0+r)*Nn + k0 + 2*k2];
            *(float2*)&sA[r*SPA + 2*k2] = v;
        }
        // X tile 32x80 -> transposed [c][k]
        #pragma unroll
        for (int p = 0; p < 20; p++){
            int e = t + p*128;          // 2560
            int k = e/80, c = e%80;
            sXT[c*SPA + k] = Xb[(size_t)(k0+k)*CSTR + c];
        }
        __syncthreads();
        #pragma unroll 4
        for (int k2 = 0; k2 < 16; k2++){
            int kk = 2*k2;
            ull av[8], xv[10];
            #pragma unroll
            for (int i = 0; i < 8; i++) av[i] = *(const ull*)&sA[(ty*8+i)*SPA + kk];
            #pragma unroll
            for (int j = 0; j < 10; j++) xv[j] = *(const ull*)&sXT[(tx*10+j)*SPA + kk];
            #pragma unroll
            for (int i = 0; i < 8; i++)
                #pragma unroll
                for (int j = 0; j < 10; j++)
                    ffma2(acc[i][j], av[i], xv[j]);
        }
        __syncthreads();
    }

    // rowsum from ones-col 79 (thread tx==7, j==9): acc = rowsum - 1
    if (tx == 7){
        #pragma unroll
        for (int i = 0; i < 8; i++) srs[ty*8 + i] = hsum(acc[i][9]) + 1.f;
    }
    __syncthreads();

    #pragma unroll
    for (int i = 0; i < 8; i++){
        int r = row0 + ty*8 + i;
        float inv = 1.f/srs[ty*8 + i];
        #pragma unroll
        for (int m = 0; m < 5; m++){
            int c = tx*10 + 2*m;
            float2 xr = *(const float2*)&Xb[(size_t)r*CSTR + c];
            float2 o;
            o.x = (hsum(acc[i][2*m  ]) + xr.x)*inv;
            o.y = (hsum(acc[i][2*m+1]) + xr.y)*inv;
            *(float2*)&Y[((size_t)b*Nn + r)*CSTR + c] = o;
        }
    }
}

// ---------------- K5: gate node-GEMM -> z,r; builds cand (col79=1) ----------------
__global__ __launch_bounds__(128) void k_gate(const float* __restrict__ x,
                                              const float* __restrict__ state)
{
    extern __shared__ float sm[];
    float* sW0 = sm;
    float* sW1 = sm + COG;
    float* sX  = sm + 2*COG;
    float* sAX = sm + 2*COG + 2112;
    int n = blockIdx.x, t = threadIdx.x;
    int bg = t >> 5, og = t & 31;

    {
        float4* d0 = (float4*)sW0; const float4* s0 = (const float4*)(g_Wg0 + (size_t)n*COG);
        float4* d1 = (float4*)sW1; const float4* s1 = (const float4*)(g_Wg1 + (size_t)n*COG);
        for (int e = t; e < COG/4; e += 128){ d0[e] = s0[e]; d1[e] = s1[e]; }
    }
    for (int e = t; e < 32*66; e += 128){
        int bi = e/66, i = e%66;
        sX [e] = g_ins[((size_t)bi*Nn + n)*CSTR + i];
        sAX[e] = g_ax [((size_t)bi*Nn + n)*CSTR + i];
    }
    __syncthreads();

    float4 acc[8] = {};
    #pragma unroll 2
    for (int i = 0; i < 66; i++){
        float4 w0 = ((const float4*)sW0)[i*32 + og];
        float4 w1 = ((const float4*)sW1)[i*32 + og];
        #pragma unroll
        for (int bb = 0; bb < 8; bb++){
            int bi = bg*8 + bb;
            float xv = sX[bi*66 + i], av = sAX[bi*66 + i];
            acc[bb].x += xv*w0.x + av*w1.x;
            acc[bb].y += xv*w0.y + av*w1.y;
            acc[bb].z += xv*w0.z + av*w1.z;
            acc[bb].w += xv*w0.w + av*w1.w;
        }
    }
    float4 bias = *(const float4*)(g_bg + n*OGg + og*4);
    int o0 = og*4;
    #pragma unroll
    for (int bb = 0; bb < 8; bb++){
        int bi = bg*8 + bb;
        size_t bn = (size_t)bi*Nn + n;
        float vals[4] = { acc[bb].x + bias.x, acc[bb].y + bias.y,
                          acc[bb].z + bias.z, acc[bb].w + bias.w };
        #pragma unroll
        for (int c = 0; c < 4; c++){
            float zz = sigm(vals[c]);
            int o = o0 + c;
            if (o < 64) g_cand[bn*CSTR + 2 + o] = zz * state[bn*64 + o];
            else        g_r  [bn*64 + (o - 64)] = zz;
        }
    }
    if (og == 0){
        #pragma unroll
        for (int bb = 0; bb < 8; bb++){
            size_t bn = (size_t)(bg*8 + bb)*Nn + n;
            g_cand[bn*CSTR + 0] = x[bn*2 + 0];
            g_cand[bn*CSTR + 1] = x[bn*2 + 1];
            #pragma unroll
            for (int c = 66; c < 80; c++) g_cand[bn*CSTR + c] = (c == 79) ? 1.f : 0.f;
        }
    }
}

// ---------------- K8: upd node-GEMM -> hc; final out ----------------
__global__ __launch_bounds__(128) void k_upd(const float* __restrict__ state,
                                             float* __restrict__ out)
{
    extern __shared__ float sm[];
    float* sW0 = sm;
    float* sW1 = sm + COU;
    float* sX  = sm + 2*COU;
    float* sAX = sm + 2*COU + 2112;
    int n = blockIdx.x, t = threadIdx.x;
    int bg = t >> 5, og = t & 31;

    {
        float4* d0 = (float4*)sW0; const float4* s0 = (const float4*)(g_Wu0 + (size_t)n*COU);
        float4* d1 = (float4*)sW1; const float4* s1 = (const float4*)(g_Wu1 + (size_t)n*COU);
        for (int e = t; e < COU/4; e += 128){ d0[e] = s0[e]; d1[e] = s1[e]; }
    }
    for (int e = t; e < 32*66; e += 128){
        int bi = e/66, i = e%66;
        sX [e] = g_cand[((size_t)bi*Nn + n)*CSTR + i];
        sAX[e] = g_axc [((size_t)bi*Nn + n)*CSTR + i];
    }
    __syncthreads();

    float2 acc[8] = {};
    #pragma unroll 2
    for (int i = 0; i < 66; i++){
        float2 w0 = ((const float2*)sW0)[i*32 + og];
        float2 w1 = ((const float2*)sW1)[i*32 + og];
        #pragma unroll
        for (int bb = 0; bb < 8; bb++){
            int bi = bg*8 + bb;
            float xv = sX[bi*66 + i], av = sAX[bi*66 + i];
            acc[bb].x += xv*w0.x + av*w1.x;
            acc[bb].y += xv*w0.y + av*w1.y;
        }
    }
    float2 bias = ((const float2*)(g_bu + n*OUu))[og];
    #pragma unroll
    for (int bb = 0; bb < 8; bb++){
        int bi = bg*8 + bb;
        size_t bn = (size_t)bi*Nn + n;
        #pragma unroll
        for (int c = 0; c < 2; c++){
            int o = og*2 + c;
            float hc = tanhf((c ? acc[bb].y + bias.y : acc[bb].x + bias.x));
            float rr = g_r[bn*64 + o];
            float sv = state[bn*64 + o];
            out[bn*64 + o] = rr*sv + (1.f - rr)*hc;
        }
    }
}

// ---------------- launcher ----------------
extern "C" void kernel_launch(void* const* d_in, const int* in_sizes, int n_in,
                              void* d_out, int out_size)
{
    const float* x      = (const float*)d_in[0];
    const float* state  = (const float*)d_in[1];
    const float* ne0    = (const float*)d_in[2];
    const float* ne1    = (const float*)d_in[3];
    const float* ne2    = (const float*)d_in[4];
    const float* f1w1   = (const float*)d_in[5];
    const float* f1b1   = (const float*)d_in[6];
    const float* f1w2   = (const float*)d_in[7];
    const float* f1b2   = (const float*)d_in[8];
    const float* f1w3   = (const float*)d_in[9];
    const float* f1b3   = (const float*)d_in[10];
    const float* f2w1   = (const float*)d_in[11];
    const float* f2b1   = (const float*)d_in[12];
    const float* f2w2   = (const float*)d_in[13];
    const float* f2b2   = (const float*)d_in[14];
    const float* f2w3   = (const float*)d_in[15];
    const float* f2b3   = (const float*)d_in[16];
    const float* gate_w = (const float*)d_in[17];
    const float* gate_b = (const float*)d_in[18];
    const float* upd_w  = (const float*)d_in[19];
    const float* upd_b  = (const float*)d_in[20];
    float* out = (float*)d_out;

    cudaFuncSetAttribute(k_gate, cudaFuncAttributeMaxDynamicSharedMemorySize, (2*COG + 2*2112)*4);
    cudaFuncSetAttribute(k_upd,  cudaFuncAttributeMaxDynamicSharedMemorySize, (2*COU + 2*2112)*4);
    cudaFuncSetAttribute(k_adj,  cudaFuncAttributeMaxDynamicSharedMemorySize, 2*128*ADJ_SP*4);

    k_prep<<<256, 128>>>(x, state, ne0, ne1,
                         f1w1, f1b1, f1w2, f1b2, f1w3, f1b3,
                         f2w1, f2b1, f2w2, f2b2, f2w3, f2b3);
    k_wmix<COG, true ><<<dim3(COG/128, Nn/64), 128>>>(gate_w, ne2);
    k_wmix<COU, false><<<dim3(COU/128, Nn/64), 128>>>(upd_w,  ne2);
    k_biases<<<Nn, 192>>>(gate_b, upd_b, ne2);
    k_adj<<<dim3(8, 8, Bb), 256, 2*128*ADJ_SP*4>>>();
    k_spmm<false><<<dim3(8, Bb), 128>>>();
    k_gate<<<Nn, 128, (2*COG + 2*2112)*4>>>(x, state);
    k_spmm<true><<<dim3(8, Bb), 128>>>();
    k_upd<<<Nn, 128, (2*COU + 2*2112)*4>>>(state, out);
}